// round 2
// baseline (speedup 1.0000x reference)
#include <cuda_runtime.h>
#include <cuda_bf16.h>
#include <cstdint>

// QuantizedLinear: out[N, OUT] = x[N, IN] @ dequant(w_packed)^T + bias
//   dequant: W[o, i] = (nibble(o, i) - 8) * w_scales[o]
//   nibble: w_packed[o, i/2] int32 holds a uint8 byte; low nibble -> even i,
//           high nibble -> odd i.
//
// Strategy: compute integer-valued GEMM acc = x @ (q - 8)^T in fp32,
// apply scale/bias in the epilogue (scale factors out of the K reduction).
//
// Tiling: 128x128 block tile, BK=32, 256 threads, 8x8 per-thread micro-tile.

#define BM 128   // n-tile
#define BN 128   // o-tile
#define BK 32    // k-tile
#define PAD 4    // smem row padding (row stride 132 floats, keeps 16B alignment)

__global__ __launch_bounds__(256, 2)
void qlinear_simt_kernel(const float* __restrict__ x,
                         const int*   __restrict__ wp,
                         const float* __restrict__ w_scales,
                         const float* __restrict__ bias,
                         float* __restrict__ out,
                         int N, int IN, int OUT)
{
    __shared__ float xs[BK][BM + PAD];   // xs[k][n]  (x transposed into smem)
    __shared__ float wq[BK][BN + PAD];   // wq[k][o]  (dequantized nibble - 8)

    const int t    = threadIdx.x;
    const int bo   = blockIdx.x;         // o-tile index
    const int bn   = blockIdx.y;         // n-tile index
    const int trow = t >> 4;             // 0..15  -> n micro-tile
    const int tcol = t & 15;             // 0..15  -> o micro-tile

    const int IN2 = IN >> 1;

    const float* xg = x  + (size_t)(bn * BM) * IN;
    const int*   wg = wp + (size_t)(bo * BN) * IN2;

    float acc[8][8];
#pragma unroll
    for (int i = 0; i < 8; i++)
#pragma unroll
        for (int j = 0; j < 8; j++)
            acc[i][j] = 0.0f;

    for (int k0 = 0; k0 < IN; k0 += BK) {
        // ---- load x tile: 128 rows x 32 k (float4 per thread x4) ----
#pragma unroll
        for (int i = 0; i < 4; i++) {
            int f  = t + i * 256;        // 0..1023
            int r  = f >> 3;             // row in tile (n), 0..127
            int c4 = f & 7;              // float4 index in k, 0..7
            float4 v = *(const float4*)(xg + (size_t)r * IN + k0 + c4 * 4);
            int kk = c4 * 4;
            xs[kk + 0][r] = v.x;
            xs[kk + 1][r] = v.y;
            xs[kk + 2][r] = v.z;
            xs[kk + 3][r] = v.w;
        }
        // ---- load + unpack w tile: 128 rows x 16 int32 (= 32 k) ----
#pragma unroll
        for (int i = 0; i < 2; i++) {
            int f  = t + i * 256;        // 0..511
            int r  = f >> 2;             // row in tile (o), 0..127
            int c4 = f & 3;              // int4 index, 0..3
            int4 v = *(const int4*)(wg + (size_t)r * IN2 + (k0 >> 1) + c4 * 4);
            int kk = c4 * 8;
            wq[kk + 0][r] = (float)(( v.x        & 0xF) - 8);
            wq[kk + 1][r] = (float)(((v.x >> 4)  & 0xF) - 8);
            wq[kk + 2][r] = (float)(( v.y        & 0xF) - 8);
            wq[kk + 3][r] = (float)(((v.y >> 4)  & 0xF) - 8);
            wq[kk + 4][r] = (float)(( v.z        & 0xF) - 8);
            wq[kk + 5][r] = (float)(((v.z >> 4)  & 0xF) - 8);
            wq[kk + 6][r] = (float)(( v.w        & 0xF) - 8);
            wq[kk + 7][r] = (float)(((v.w >> 4)  & 0xF) - 8);
        }
        __syncthreads();

        // ---- compute: 8x8 micro-tile over BK ----
#pragma unroll 8
        for (int kk = 0; kk < BK; kk++) {
            float a[8], b[8];
            *(float4*)&a[0] = *(const float4*)&xs[kk][trow * 4];
            *(float4*)&a[4] = *(const float4*)&xs[kk][trow * 4 + 64];
            *(float4*)&b[0] = *(const float4*)&wq[kk][tcol * 4];
            *(float4*)&b[4] = *(const float4*)&wq[kk][tcol * 4 + 64];
#pragma unroll
            for (int i = 0; i < 8; i++)
#pragma unroll
                for (int j = 0; j < 8; j++)
                    acc[i][j] = fmaf(a[i], b[j], acc[i][j]);
        }
        __syncthreads();
    }

    // ---- epilogue: out = scale[o] * acc + bias[o] ----
    float sc[8], bs[8];
#pragma unroll
    for (int j = 0; j < 8; j++) {
        int o = bo * BN + tcol * 4 + (j & 3) + ((j >= 4) ? 64 : 0);
        sc[j] = w_scales[o];
        bs[j] = bias[o];
    }
#pragma unroll
    for (int i = 0; i < 8; i++) {
        int n = bn * BM + trow * 4 + (i & 3) + ((i >= 4) ? 64 : 0);
        float* orow = out + (size_t)n * OUT + bo * BN;
        float4 r0, r1;
        r0.x = fmaf(acc[i][0], sc[0], bs[0]);
        r0.y = fmaf(acc[i][1], sc[1], bs[1]);
        r0.z = fmaf(acc[i][2], sc[2], bs[2]);
        r0.w = fmaf(acc[i][3], sc[3], bs[3]);
        r1.x = fmaf(acc[i][4], sc[4], bs[4]);
        r1.y = fmaf(acc[i][5], sc[5], bs[5]);
        r1.z = fmaf(acc[i][6], sc[6], bs[6]);
        r1.w = fmaf(acc[i][7], sc[7], bs[7]);
        *(float4*)(orow + tcol * 4)      = r0;
        *(float4*)(orow + tcol * 4 + 64) = r1;
    }
}

extern "C" void kernel_launch(void* const* d_in, const int* in_sizes, int n_in,
                              void* d_out, int out_size)
{
    const float* x        = (const float*)d_in[0];
    const int*   w_packed = (const int*)  d_in[1];
    const float* w_scales = (const float*)d_in[2];
    const float* bias     = (const float*)d_in[3];
    float*       out      = (float*)d_out;

    // Derive shapes: w_scales has OUT elements; w_packed = OUT * IN/2;
    // x = N * IN.
    const int OUT = in_sizes[2];
    const int IN  = (int)(2LL * in_sizes[1] / OUT);
    const int N   = (int)((long long)in_sizes[0] / IN);

    dim3 grid(OUT / BN, N / BM);
    dim3 block(256);
    qlinear_simt_kernel<<<grid, block>>>(x, w_packed, w_scales, bias, out,
                                         N, IN, OUT);
}

// round 6
// speedup vs baseline: 5.4488x; 5.4488x over previous
#include <cuda_runtime.h>
#include <cuda_fp16.h>
#include <cstdint>

// QuantizedLinear: out[N,OUT] = x[N,IN] @ dequant(w_packed)^T + bias
//   W[o,i] = (nib(o,i)-8)*scale[o]; low nibble -> even i.
//   NOTE: w_packed is int32 with ONE byte payload per element (values 0..255),
//   i.e. 2 nibbles per int32. Pre-pass repacks to dense uint8.
//
// tcgen05 unavailable (harness PTX targets sm_103, not sm_103a) -> legacy
// HMMA mma.sync.m16n8k16 f16*f16+f32. acc = x_f16 @ (q-8)^T, scale/bias in
// epilogue. Packed bytes unpack straight into B fragment registers (one byte
// == one b32 fragment reg: adjacent-k half2).

#define NR 4096
#define KD 4096
#define OD 4096
#define BM 128
#define BN 128
#define BK 32
#define NIT (KD / BK)
#define NSTG 4

// per-stage smem: A tile 128 rows x 32 halves, row stride 80 B; B tile
// 128 rows x 16 packed bytes.
#define A_STRIDE 80
#define A_BYTES  (BM * A_STRIDE)        // 10240
#define STG_STR  (A_BYTES + BN * 16)    // 12288
// total 4*12288 = 49152 bytes static smem

__device__ __half   g_xh[(size_t)NR * KD];
__device__ uint8_t  g_wb[(size_t)OD * (KD / 2)];

__device__ __forceinline__ uint32_t s2u(const void* p) {
    uint32_t a;
    asm("{ .reg .u64 t; cvta.to.shared.u64 t, %1; cvt.u32.u64 %0, t; }"
        : "=r"(a) : "l"(p));
    return a;
}

#define CP16(dst, src) \
    asm volatile("cp.async.cg.shared.global [%0], [%1], 16;" \
                 :: "r"(dst), "l"(src) : "memory")
#define CPCOMMIT() asm volatile("cp.async.commit_group;" ::: "memory")
#define CPWAIT2()  asm volatile("cp.async.wait_group 2;"  ::: "memory")

// packed byte (2 nibbles) -> half2 (lo-8, hi-8). Exact: nibbles into mantissa
// of 1024.0, subtract 1032.
__device__ __forceinline__ uint32_t nib2h(uint32_t w, uint32_t sel) {
    uint32_t d = __byte_perm(w, 0, sel);            // [b, 0, b, 0]
    d = (d & 0x0000000Fu) | ((d >> 4) & 0x000F0000u) | 0x64006400u;
    const uint32_t C = 0x64086408u;
    __half2 h = __hsub2(*reinterpret_cast<__half2*>(&d),
                        *reinterpret_cast<const __half2*>(&C));
    return *reinterpret_cast<uint32_t*>(&h);
}

__device__ __forceinline__ void mma16816(float* c, const uint32_t* a,
                                         uint32_t b0, uint32_t b1) {
    asm volatile(
        "mma.sync.aligned.m16n8k16.row.col.f32.f16.f16.f32 "
        "{%0,%1,%2,%3}, {%4,%5,%6,%7}, {%8,%9}, {%0,%1,%2,%3};"
        : "+f"(c[0]), "+f"(c[1]), "+f"(c[2]), "+f"(c[3])
        : "r"(a[0]), "r"(a[1]), "r"(a[2]), "r"(a[3]), "r"(b0), "r"(b1));
}

__global__ void cvt_x(const float* __restrict__ x) {
    size_t i = ((size_t)blockIdx.x * 256 + threadIdx.x) * 4;
    float4 v = *(const float4*)(x + i);
    *(__half2*)(g_xh + i)     = __floats2half2_rn(v.x, v.y);
    *(__half2*)(g_xh + i + 2) = __floats2half2_rn(v.z, v.w);
}

// w_packed int32 (one byte payload each) -> dense uint8
__global__ void repack_w(const int* __restrict__ wp) {
    size_t i = ((size_t)blockIdx.x * 256 + threadIdx.x) * 16;
    const int4* src = (const int4*)(wp + i);
    uint4 o;
    int4 v0 = src[0], v1 = src[1], v2 = src[2], v3 = src[3];
    o.x = (uint32_t)(v0.x & 0xFF) | ((uint32_t)(v0.y & 0xFF) << 8) |
          ((uint32_t)(v0.z & 0xFF) << 16) | ((uint32_t)v0.w << 24);
    o.y = (uint32_t)(v1.x & 0xFF) | ((uint32_t)(v1.y & 0xFF) << 8) |
          ((uint32_t)(v1.z & 0xFF) << 16) | ((uint32_t)v1.w << 24);
    o.z = (uint32_t)(v2.x & 0xFF) | ((uint32_t)(v2.y & 0xFF) << 8) |
          ((uint32_t)(v2.z & 0xFF) << 16) | ((uint32_t)v2.w << 24);
    o.w = (uint32_t)(v3.x & 0xFF) | ((uint32_t)(v3.y & 0xFF) << 8) |
          ((uint32_t)(v3.z & 0xFF) << 16) | ((uint32_t)v3.w << 24);
    *(uint4*)(g_wb + i) = o;
}

__global__ void __launch_bounds__(256, 2)
qmma_kernel(const float* __restrict__ wscale,
            const float* __restrict__ wbias, float* __restrict__ out)
{
    __shared__ __align__(16) char sm[NSTG * STG_STR];

    const int t   = threadIdx.x;
    const int wid = t >> 5, lid = t & 31;
    const int wm  = wid >> 2;            // 0..1 -> m offset wm*64
    const int wn  = wid & 3;             // 0..3 -> n offset wn*32
    const int g   = lid >> 2;            // 0..7
    const int c   = lid & 3;             // 0..3
    const int o0  = blockIdx.x * BN;
    const int n0  = blockIdx.y * BM;
    const uint32_t sb = s2u(sm);
    const uint32_t sel = 0x4040u | ((uint32_t)c << 8) | (uint32_t)c;

    const __half*  xg = g_xh + (size_t)n0 * KD;
    const uint8_t* wg = g_wb + (size_t)o0 * (KD / 2);

    float acc[4][4][4];
#pragma unroll
    for (int mi = 0; mi < 4; mi++)
#pragma unroll
        for (int nj = 0; nj < 4; nj++)
#pragma unroll
            for (int r = 0; r < 4; r++)
                acc[mi][nj][r] = 0.0f;

    auto issue = [&](int s, int k0) {
        uint32_t sa = sb + s * STG_STR;
#pragma unroll
        for (int j = 0; j < 2; j++) {
            int idx = t + j * 256;           // 0..511
            int r = idx >> 2, cc = idx & 3;  // row, 16B-chunk
            CP16(sa + r * A_STRIDE + cc * 16,
                 xg + (size_t)r * KD + k0 + cc * 8);
        }
        if (t < BN)
            CP16(sa + A_BYTES + t * 16, wg + (size_t)t * (KD / 2) + (k0 >> 1));
    };

#pragma unroll
    for (int s = 0; s < NSTG - 1; s++) { issue(s, s * BK); CPCOMMIT(); }

#pragma unroll 1
    for (int i = 0; i < NIT; i++) {
        CPWAIT2();
        __syncthreads();

        const uint32_t A  = sb + (i & (NSTG - 1)) * STG_STR;
        const uint32_t Bb = A + A_BYTES;

        uint32_t breg[2][4][2];
#pragma unroll
        for (int nj = 0; nj < 4; nj++) {
            int row = wn * 32 + nj * 8 + g;
            uint4 w;
            asm volatile("ld.shared.v4.u32 {%0,%1,%2,%3}, [%4];"
                         : "=r"(w.x), "=r"(w.y), "=r"(w.z), "=r"(w.w)
                         : "r"(Bb + row * 16));
            breg[0][nj][0] = nib2h(w.x, sel);
            breg[0][nj][1] = nib2h(w.y, sel);
            breg[1][nj][0] = nib2h(w.z, sel);
            breg[1][nj][1] = nib2h(w.w, sel);
        }

#pragma unroll
        for (int ks = 0; ks < 2; ks++) {
#pragma unroll
            for (int mi = 0; mi < 4; mi++) {
                int row = wm * 64 + mi * 16 + g;
                uint32_t base = A + row * A_STRIDE + ks * 32 + c * 4;
                uint32_t a[4];
                asm volatile("ld.shared.b32 %0, [%1];" : "=r"(a[0]) : "r"(base));
                asm volatile("ld.shared.b32 %0, [%1];" : "=r"(a[1]) : "r"(base + 8 * A_STRIDE));
                asm volatile("ld.shared.b32 %0, [%1];" : "=r"(a[2]) : "r"(base + 16));
                asm volatile("ld.shared.b32 %0, [%1];" : "=r"(a[3]) : "r"(base + 8 * A_STRIDE + 16));
#pragma unroll
                for (int nj = 0; nj < 4; nj++)
                    mma16816(acc[mi][nj], a, breg[ks][nj][0], breg[ks][nj][1]);
            }
        }
        __syncthreads();

        int nx = i + NSTG - 1;
        if (nx < NIT) issue(nx & (NSTG - 1), nx * BK);
        CPCOMMIT();
    }

    // ---- epilogue: scale/bias, direct float2 stores ----
#pragma unroll
    for (int nj = 0; nj < 4; nj++) {
        int col = o0 + wn * 32 + nj * 8 + c * 2;
        float s0 = __ldg(wscale + col), s1 = __ldg(wscale + col + 1);
        float b0 = __ldg(wbias + col),  b1 = __ldg(wbias + col + 1);
#pragma unroll
        for (int mi = 0; mi < 4; mi++) {
            int row = n0 + wm * 64 + mi * 16 + g;
            float2 v0, v1;
            v0.x = fmaf(acc[mi][nj][0], s0, b0);
            v0.y = fmaf(acc[mi][nj][1], s1, b1);
            v1.x = fmaf(acc[mi][nj][2], s0, b0);
            v1.y = fmaf(acc[mi][nj][3], s1, b1);
            *(float2*)(out + (size_t)row * OD + col)       = v0;
            *(float2*)(out + (size_t)(row + 8) * OD + col) = v1;
        }
    }
}

extern "C" void kernel_launch(void* const* d_in, const int* in_sizes, int n_in,
                              void* d_out, int out_size)
{
    const float* x      = (const float*)d_in[0];
    const int*   wpk    = (const int*)  d_in[1];
    const float* wscale = (const float*)d_in[2];
    const float* wbias  = (const float*)d_in[3];
    float*       out    = (float*)d_out;

    cvt_x<<<((size_t)NR * KD) / 1024, 256>>>(x);
    repack_w<<<((size_t)OD * (KD / 2)) / 4096, 256>>>(wpk);

    dim3 grid(OD / BN, NR / BM);
    qmma_kernel<<<grid, 256>>>(wscale, wbias, out);
}